// round 9
// baseline (speedup 1.0000x reference)
#include <cuda_runtime.h>
#include <cuda_bf16.h>
#include <stdint.h>

// Periodic radius-graph: B=4, N=512, K=27.
// Outputs concatenated in d_out (float32):
//   [0,      S)   distances   [B,N,N,K]
//   [S,     4S)   distance_vec[B,N,N,K,3]
//   [4S,    5S)   mask        [B,N,N,K]  (0.0/1.0)
//   [5S, 5S+81B)  offset_cart [B,27,3]
// with S = B*N*N*K.
//
// Persistent single-wave launch: grid = 8*num_SMs blocks, each handling a
// balanced contiguous range of "chunks" (768 elems each) from the global
// chunk space (B*N*18 chunks). dist/mask: direct coalesced STG. vec: smem
// staged, drained by cp.async.bulk shared->global (TMA), double-buffered.

#define KIMG   27
#define MAXN   512
#define TPB    256
#define CH     768            // elems per chunk (3 per thread)
#define CPB    18             // chunks per (b,i): N*KIMG / CH = 13824/768

__device__ __forceinline__ void bulk_s2g(void* gdst, uint32_t ssrc, uint32_t bytes) {
    asm volatile(
        "cp.async.bulk.global.shared::cta.bulk_group [%0], [%1], %2;"
        :: "l"(gdst), "r"(ssrc), "r"(bytes) : "memory");
}

__global__ __launch_bounds__(TPB)
void radius_graph_kernel(const float* __restrict__ pos,
                         const float* __restrict__ cell,
                         float* __restrict__ out,
                         int B, int N, size_t S, int total_chunks)
{
    __shared__ __align__(16) float4 spos4[MAXN];      // 8 KB, current structure
    __shared__ __align__(16) float4 soff4[4][KIMG];   // 1.7 KB, all structures
    __shared__ __align__(16) float  svec[2][CH * 3];  // 2 x 9 KB vec staging

    const int G = gridDim.x;
    const int g = blockIdx.x;

    // 27 cartesian image offsets for ALL structures (computed once).
    // off[b][k][d] = sum_c frac[k][c] * cell[b][c][d]
    if (threadIdx.x < 4 * KIMG) {
        const int bb = threadIdx.x / KIMG;
        const int k  = threadIdx.x - bb * KIMG;
        if (bb < B) {
            const int f0 = (k / 9) - 1;
            const int f1 = ((k / 3) % 3) - 1;
            const int f2 = (k % 3) - 1;
            const float* cb = cell + bb * 9;
            float ox = (float)f0 * cb[0] + (float)f1 * cb[3] + (float)f2 * cb[6];
            float oy = (float)f0 * cb[1] + (float)f1 * cb[4] + (float)f2 * cb[7];
            float oz = (float)f0 * cb[2] + (float)f1 * cb[5] + (float)f2 * cb[8];
            soff4[bb][k] = make_float4(ox, oy, oz, 0.0f);
        }
    }

    // Balanced chunk range for this block.
    const int lo = (int)((long long)g       * total_chunks / G);
    const int hi = (int)((long long)(g + 1) * total_chunks / G);

    const int NK = N * KIMG;

    float* __restrict__ dist_out = out;
    float* __restrict__ vec_out  = out + S;
    float* __restrict__ mask_out = out + 4 * S;

    uint32_t svec_addr[2];
    svec_addr[0] = (uint32_t)__cvta_generic_to_shared(&svec[0][0]);
    svec_addr[1] = (uint32_t)__cvta_generic_to_shared(&svec[1][0]);

    int cur_b = -1;
    int p = 0;
    int issued = 0;

    __syncthreads();   // soff4 ready

    for (int ch = lo; ch < hi; ch++) {
        const int bi = ch / CPB;              // which (b,i)
        const int c0 = (ch - bi * CPB) * CH;  // element offset within (b,i)
        const int b  = bi / N;
        const int i  = bi - b * N;

        // Buffer p was handed to TMA 2 chunks ago; ensure drained.
        if (issued >= 2 && threadIdx.x == 0)
            asm volatile("cp.async.bulk.wait_group 1;" ::: "memory");
        __syncthreads();

        // (Re)load this structure's positions (happens <= 2 times per block).
        if (b != cur_b) {
            const float* posb = pos + (size_t)b * N * 3;
            for (int t = threadIdx.x; t < N; t += TPB)
                spos4[t] = make_float4(posb[t * 3 + 0], posb[t * 3 + 1],
                                       posb[t * 3 + 2], 0.0f);
            cur_b = b;
            __syncthreads();
        }

        const float4 pi4 = spos4[i];
        const float pix = pi4.x, piy = pi4.y, piz = pi4.z;
        const float4* soffb = soff4[b];
        const size_t base = (size_t)bi * (size_t)NK;

        // ---- compute: dist/mask direct coalesced, vec -> smem buffer p ----
        float* sv = svec[p];
        #pragma unroll
        for (int q = 0; q < CH / TPB; q++) {
            const int lt = threadIdx.x + q * TPB;
            const int t  = c0 + lt;

            const int j = t / KIMG;
            const int k = t - j * KIMG;

            const float4 pj = spos4[j];
            const float4 ok = soffb[k];

            // vec = (pos_j + offset_k) - pos_i  (reference association order)
            const float vx = (pj.x + ok.x) - pix;
            const float vy = (pj.y + ok.y) - piy;
            const float vz = (pj.z + ok.z) - piz;

            const float sq = vx * vx + vy * vy + vz * vz;
            const bool  m  = (sq > 1e-8f) && (sq <= 25.0f);
            const float mf = m ? 1.0f : 0.0f;
            const float dd = m ? sqrtf(sq) : 0.0f;

            const size_t idx = base + (size_t)t;
            dist_out[idx] = dd;
            mask_out[idx] = mf;
            // conflict-free smem: bank = (3*lt + c) % 32, gcd(3,32)=1
            sv[lt * 3 + 0] = vx * mf;
            sv[lt * 3 + 1] = vy * mf;
            sv[lt * 3 + 2] = vz * mf;
        }

        // Order generic-proxy STS before async-proxy TMA read.
        asm volatile("fence.proxy.async.shared::cta;" ::: "memory");
        __syncthreads();

        // ---- drain: hand the 9216-B chunk to the TMA engine ----
        if (threadIdx.x == 0) {
            bulk_s2g(vec_out + (base + (size_t)c0) * 3, svec_addr[p], CH * 3 * 4);
            asm volatile("cp.async.bulk.commit_group;" ::: "memory");
        }
        p ^= 1;
        issued++;
    }

    // offset_cart tail: first B blocks each write one structure's 81 floats.
    if (g < B && threadIdx.x < KIMG) {
        const float4 o4 = soff4[g][threadIdx.x];
        float* dst = out + 5 * S + (size_t)g * (KIMG * 3) + threadIdx.x * 3;
        dst[0] = o4.x; dst[1] = o4.y; dst[2] = o4.z;
    }

    // Ensure all bulk stores complete before the block exits.
    if (threadIdx.x == 0)
        asm volatile("cp.async.bulk.wait_group 0;" ::: "memory");
}

extern "C" void kernel_launch(void* const* d_in, const int* in_sizes, int n_in,
                              void* d_out, int out_size)
{
    const float* pos  = (const float*)d_in[0];  // [B, N, 3]
    const float* cell = (const float*)d_in[1];  // [B, 3, 3]

    const int B = in_sizes[1] / 9;              // 4
    const int N = in_sizes[0] / (3 * B);        // 512
    const size_t S = (size_t)B * N * N * KIMG;  // 28,311,552
    const int total_chunks = B * N * CPB;       // 36864

    int dev = 0, sms = 148;
    cudaGetDevice(&dev);
    cudaDeviceGetAttribute(&sms, cudaDevAttrMultiProcessorCount, dev);
    int G = 8 * sms;                            // one full resident wave
    if (G > total_chunks) G = total_chunks;

    float* out = (float*)d_out;

    radius_graph_kernel<<<G, TPB>>>(pos, cell, out, B, N, S, total_chunks);
}

// round 10
// speedup vs baseline: 1.2218x; 1.2218x over previous
#include <cuda_runtime.h>
#include <cuda_bf16.h>
#include <stdint.h>

// Periodic radius-graph: B=4, N=512, K=27.
// Outputs concatenated in d_out (float32):
//   [0,      S)   distances   [B,N,N,K]
//   [S,     4S)   distance_vec[B,N,N,K,3]
//   [4S,    5S)   mask        [B,N,N,K]  (0.0/1.0)
//   [5S, 5S+81B)  offset_cart [B,27,3]
// with S = B*N*N*K.
//
// dist/mask: direct coalesced streaming stores (__stcs, evict-first — data is
// dead on arrival in L2). vec: smem-staged, drained by cp.async.bulk
// shared->global (TMA), double-buffered. One block per (b,i).

#define KIMG   27
#define MAXN   512
#define TPB    256
#define CH     768                 // elems/chunk = 3 per thread; NK/CH = 18
#define NCHUNK (MAXN * KIMG / CH)  // 18

__device__ __forceinline__ void bulk_s2g(void* gdst, uint32_t ssrc, uint32_t bytes) {
    asm volatile(
        "cp.async.bulk.global.shared::cta.bulk_group [%0], [%1], %2;"
        :: "l"(gdst), "r"(ssrc), "r"(bytes) : "memory");
}

__global__ __launch_bounds__(TPB)
void radius_graph_kernel(const float* __restrict__ pos,
                         const float* __restrict__ cell,
                         float* __restrict__ out,
                         int B, int N, size_t S)
{
    __shared__ __align__(16) float4 spos4[MAXN];      // 8 KB (xyz + pad)
    __shared__ __align__(16) float4 soff4[KIMG];      // 432 B
    __shared__ __align__(16) float  svec[2][CH * 3];  // 2 x 9 KB vec staging

    const int bi = blockIdx.x;        // 0 .. B*N-1
    const int b  = bi / N;
    const int i  = bi - b * N;

    // Load this structure's positions into shared memory as float4
    const float* posb = pos + (size_t)b * N * 3;
    for (int t = threadIdx.x; t < N; t += TPB)
        spos4[t] = make_float4(posb[t * 3 + 0], posb[t * 3 + 1], posb[t * 3 + 2], 0.0f);

    // 27 cartesian image offsets: off[k][d] = sum_c frac[k][c]*cell[b][c][d]
    if (threadIdx.x < KIMG) {
        const int k = threadIdx.x;
        const int f0 = (k / 9) - 1;
        const int f1 = ((k / 3) % 3) - 1;
        const int f2 = (k % 3) - 1;
        const float* cb = cell + b * 9;
        float ox = (float)f0 * cb[0] + (float)f1 * cb[3] + (float)f2 * cb[6];
        float oy = (float)f0 * cb[1] + (float)f1 * cb[4] + (float)f2 * cb[7];
        float oz = (float)f0 * cb[2] + (float)f1 * cb[5] + (float)f2 * cb[8];
        soff4[k] = make_float4(ox, oy, oz, 0.0f);
    }
    __syncthreads();

    const float4 pi4 = spos4[i];
    const float pix = pi4.x, piy = pi4.y, piz = pi4.z;

    float* __restrict__ dist_out = out;
    float* __restrict__ vec_out  = out + S;
    float* __restrict__ mask_out = out + 4 * S;

    const int    NK   = N * KIMG;                 // 13824 = 18 * CH
    const size_t base = (size_t)bi * (size_t)NK;

    uint32_t svec_addr[2];
    svec_addr[0] = (uint32_t)__cvta_generic_to_shared(&svec[0][0]);
    svec_addr[1] = (uint32_t)__cvta_generic_to_shared(&svec[1][0]);

    int p = 0;
    for (int c = 0; c < NCHUNK; c++) {
        const int c0 = c * CH;

        // Buffer p was handed to the TMA engine 2 iterations ago; ensure
        // that bulk-store group has drained before overwriting it.
        if (c >= 2 && threadIdx.x == 0)
            asm volatile("cp.async.bulk.wait_group 1;" ::: "memory");
        __syncthreads();

        // ---- compute: dist/mask direct streaming stores, vec -> smem ----
        float* sv = svec[p];
        #pragma unroll
        for (int q = 0; q < CH / TPB; q++) {
            const int lt = threadIdx.x + q * TPB;
            const int t  = c0 + lt;

            const int j = t / KIMG;
            const int k = t - j * KIMG;

            const float4 pj = spos4[j];
            const float4 ok = soff4[k];

            // vec = (pos_j + offset_k) - pos_i  (reference association order)
            const float vx = (pj.x + ok.x) - pix;
            const float vy = (pj.y + ok.y) - piy;
            const float vz = (pj.z + ok.z) - piz;

            const float sq = vx * vx + vy * vy + vz * vz;
            const bool  m  = (sq > 1e-8f) && (sq <= 25.0f);
            const float mf = m ? 1.0f : 0.0f;
            const float dd = m ? sqrtf(sq) : 0.0f;

            const size_t idx = base + (size_t)t;
            __stcs(dist_out + idx, dd);   // evict-first: pure streaming write
            __stcs(mask_out + idx, mf);
            // conflict-free smem: bank = (3*lt + c) % 32, gcd(3,32)=1
            sv[lt * 3 + 0] = vx * mf;
            sv[lt * 3 + 1] = vy * mf;
            sv[lt * 3 + 2] = vz * mf;
        }

        // Order generic-proxy STS before async-proxy TMA read.
        asm volatile("fence.proxy.async.shared::cta;" ::: "memory");
        __syncthreads();

        // ---- drain: one thread hands the 9216-B chunk to the TMA engine ----
        if (threadIdx.x == 0) {
            bulk_s2g(vec_out + (base + (size_t)c0) * 3, svec_addr[p], CH * 3 * 4);
            asm volatile("cp.async.bulk.commit_group;" ::: "memory");
        }
        p ^= 1;
    }

    // offset_cart tail: the i==0 block of each structure writes 81 floats
    if (i == 0 && threadIdx.x < KIMG) {
        const float4 o4 = soff4[threadIdx.x];
        float* dst = out + 5 * S + (size_t)b * (KIMG * 3) + threadIdx.x * 3;
        dst[0] = o4.x; dst[1] = o4.y; dst[2] = o4.z;
    }

    // Ensure all bulk stores are complete before the block exits.
    if (threadIdx.x == 0)
        asm volatile("cp.async.bulk.wait_group 0;" ::: "memory");
}

extern "C" void kernel_launch(void* const* d_in, const int* in_sizes, int n_in,
                              void* d_out, int out_size)
{
    const float* pos  = (const float*)d_in[0];  // [B, N, 3]
    const float* cell = (const float*)d_in[1];  // [B, 3, 3]

    const int B = in_sizes[1] / 9;              // 4
    const int N = in_sizes[0] / (3 * B);        // 512
    const size_t S = (size_t)B * N * N * KIMG;  // 28,311,552

    float* out = (float*)d_out;

    dim3 grid(B * N);
    dim3 block(TPB);
    radius_graph_kernel<<<grid, block>>>(pos, cell, out, B, N, S);
}